// round 5
// baseline (speedup 1.0000x reference)
#include <cuda_runtime.h>
#include <math.h>

#define DD     32
#define DIMN   16
#define NTOT   4096
#define EPSV   1e-5f
#define LAM    0.1f
#define NSWEEP 6
#define WARPS_PER_BLK 8

// ---------------- scratch (device globals: no allocation allowed) -----------
__device__ float2 g_G[DIMN * DIMN];            // sum_d A_d A_d^H
__device__ float2 g_S[DD * DIMN * DIMN];       // A_d + A_d^H
__device__ float2 g_r[DD * DIMN];              // column sums of A_d
__device__ float2 g_r2[DD * DIMN];             // column sums of A_d @ A_d
__device__ double g_acc;
__device__ unsigned int g_cnt;

__device__ __forceinline__ float frcp(float a) {
    float r; asm("rcp.approx.f32 %0,%1;" : "=f"(r) : "f"(a)); return r;
}

// ---------------- kernel 0: constants from A --------------------------------
// blocks 0..31: S_d, r_d, r2_d for d = blockIdx.x
// block  32   : G = sum_d A_d A_d^H (atomics-free) + zero g_acc/g_cnt
__global__ void precompute_kernel(const float* __restrict__ Ar,
                                  const float* __restrict__ Ai) {
    __shared__ float2 sr[DIMN];
    const int t = threadIdx.x;          // 256 threads, one per (i,j)
    const int i = t >> 4, j = t & 15;

    if (blockIdx.x == DD) {
        // G[i][j] = sum_d sum_k A_d[i,k] conj(A_d[j,k])
        float gx = 0.f, gy = 0.f;
        for (int d = 0; d < DD; d++) {
            const float* ar = Ar + d * 256;
            const float* ai = Ai + d * 256;
            #pragma unroll
            for (int k = 0; k < 16; k++) {
                float axr = ar[i * 16 + k], axi = ai[i * 16 + k];
                float bxr = ar[j * 16 + k], bxi = ai[j * 16 + k];
                gx += axr * bxr + axi * bxi;
                gy += axi * bxr - axr * bxi;
            }
        }
        g_G[t] = make_float2(gx, gy);
        if (t == 0) { g_acc = 0.0; g_cnt = 0u; }
        return;
    }

    const int d = blockIdx.x;
    const float* ar = Ar + d * 256;
    const float* ai = Ai + d * 256;

    // S_d = A_d + A_d^H
    float arij = ar[i * 16 + j], aiij = ai[i * 16 + j];
    float arji = ar[j * 16 + i], aiji = ai[j * 16 + i];
    g_S[d * 256 + t] = make_float2(arij + arji, aiij - aiji);

    // r_d[j] = sum_i A_d[i,j]
    if (t < 16) {
        float2 s = make_float2(0.f, 0.f);
        #pragma unroll
        for (int ii = 0; ii < 16; ii++) {
            s.x += ar[ii * 16 + t];
            s.y += ai[ii * 16 + t];
        }
        sr[t] = s;
        g_r[d * 16 + t] = s;
    }
    __syncthreads();
    // r2_d[j] = sum_k r_d[k] * A_d[k,j]
    if (t < 16) {
        float2 s = make_float2(0.f, 0.f);
        #pragma unroll
        for (int k = 0; k < 16; k++) {
            float2 rk = sr[k];
            float axr = ar[k * 16 + t], axi = ai[k * 16 + t];
            s.x += rk.x * axr - rk.y * axi;
            s.y += rk.x * axi + rk.y * axr;
        }
        g_r2[d * 16 + t] = s;
    }
}

// ---------------- kernel 1: build H, one-sided Jacobi in registers ----------
__global__ void __launch_bounds__(WARPS_PER_BLK * 32)
solve_kernel(const float* __restrict__ X, float* __restrict__ out) {
    __shared__ float2 sH[WARPS_PER_BLK][DIMN * 17];   // build/transpose buffer
    __shared__ float2 spsi[WARPS_PER_BLK][DIMN];

    const int w    = threadIdx.x >> 5;
    const int lane = threadIdx.x & 31;
    const int n    = blockIdx.x * WARPS_PER_BLK + w;
    const unsigned FULL = 0xffffffffu;

    float2* H = sH[w];

    // ---- load x_n, ||x||^2 ----
    float x = X[n * DD + lane];
    float sx2 = x * x;
    #pragma unroll
    for (int o = 16; o > 0; o >>= 1) sx2 += __shfl_xor_sync(FULL, sx2, o);

    // ---- H = 0.5*G - 0.5*sum_d x_d S_d + (eps + 0.5*||x||^2) I ----
    {
        float2 acc[8];
        #pragma unroll
        for (int m = 0; m < 8; m++) {
            float2 g = g_G[m * 32 + lane];
            acc[m] = make_float2(0.5f * g.x, 0.5f * g.y);
        }
        #pragma unroll
        for (int d = 0; d < DD; d++) {
            float h = 0.5f * __shfl_sync(FULL, x, d);
            #pragma unroll
            for (int m = 0; m < 8; m++) {
                float2 s = g_S[d * 256 + m * 32 + lane];
                acc[m].x -= h * s.x;
                acc[m].y -= h * s.y;
            }
        }
        #pragma unroll
        for (int m = 0; m < 8; m++) {
            int e = m * 32 + lane;
            int i = e >> 4, j = e & 15;
            if (i == j) acc[m].x += EPSV + 0.5f * sx2;
            H[i * 17 + j] = acc[m];
        }
    }
    __syncwarp();

    // ---- register layout: group g = lane>>2 holds columns (2g, 2g+1);
    //      lane rl = lane&3 holds rows {4r+rl} ----
    const int g  = lane >> 2;
    const int rl = lane & 3;

    float2 T[4], B[4];
    #pragma unroll
    for (int r = 0; r < 4; r++) {
        T[r] = H[(r * 4 + rl) * 17 + 2 * g];
        B[r] = H[(r * 4 + rl) * 17 + 2 * g + 1];
    }

    // ---- one-sided Jacobi: 15 rounds/sweep (round-robin), registers only ----
    for (int it = 0; it < NSWEEP * 15; it++) {
        // Gram: (|B|^2 - |T|^2) and conj(T).B
        float df = 0.f, bx = 0.f, by = 0.f;
        #pragma unroll
        for (int r = 0; r < 4; r++) {
            df += (B[r].x * B[r].x + B[r].y * B[r].y)
                - (T[r].x * T[r].x + T[r].y * T[r].y);
            bx += T[r].x * B[r].x + T[r].y * B[r].y;   // Re conj(T).B
            by += T[r].x * B[r].y - T[r].y * B[r].x;   // Im conj(T).B
        }
        #pragma unroll
        for (int o = 1; o <= 2; o <<= 1) {
            df += __shfl_xor_sync(FULL, df, o);
            bx += __shfl_xor_sync(FULL, bx, o);
            by += __shfl_xor_sync(FULL, by, o);
        }

        // rotation params — division/sqrt-free fast path (MUFU only)
        float ab2 = bx * bx + by * by;
        float c = 1.f, wx = 0.f, wy = 0.f;
        if (ab2 > 1e-28f) {
            float rab = rsqrtf(ab2);                 // 1/|b|
            float tau = 0.5f * df * rab;
            float t2  = tau * tau + 1.f;
            float sq  = t2 * rsqrtf(t2);             // sqrt(t2)
            float den = fabsf(tau) + sq;
            float tt  = ((tau >= 0.f) ? 1.f : -1.f) * frcp(den);
            c = rsqrtf(tt * tt + 1.f);
            float inv = tt * c * rab;                // s/|b|
            wx = bx * inv; wy = by * inv;
        }

        // column update + fused round-robin permutation (circle method)
        #pragma unroll
        for (int r = 0; r < 4; r++) {
            float tx = T[r].x, ty = T[r].y;
            float bxr = B[r].x, byr = B[r].y;
            float ntx = c * tx - (wx * bxr + wy * byr);
            float nty = c * ty - (wx * byr - wy * bxr);
            float nbx = (wx * tx - wy * ty) + c * bxr;
            float nby = (wx * ty + wy * tx) + c * byr;

            float selx = (g == 0) ? nbx : ntx;
            float sely = (g == 0) ? nby : nty;
            float upx = __shfl_sync(FULL, selx, lane - 4);
            float upy = __shfl_sync(FULL, sely, lane - 4);
            float dnx = __shfl_sync(FULL, nbx, lane + 4);
            float dny = __shfl_sync(FULL, nby, lane + 4);

            T[r] = (g == 0) ? make_float2(ntx, nty) : make_float2(upx, upy);
            B[r] = (g == 7) ? make_float2(ntx, nty) : make_float2(dnx, dny);
        }
    }

    // ---- column norms, pick minimum (= min eigenvalue's column) ----
    float nT = 0.f, nB = 0.f;
    #pragma unroll
    for (int r = 0; r < 4; r++) {
        nT += T[r].x * T[r].x + T[r].y * T[r].y;
        nB += B[r].x * B[r].x + B[r].y * B[r].y;
    }
    #pragma unroll
    for (int o = 1; o <= 2; o <<= 1) {
        nT += __shfl_xor_sync(FULL, nT, o);
        nB += __shfl_xor_sync(FULL, nB, o);
    }
    float v; int tag;
    if (nB < nT) { v = nB; tag = 2 * g + 1; } else { v = nT; tag = 2 * g; }
    #pragma unroll
    for (int o = 4; o <= 16; o <<= 1) {
        float ov = __shfl_xor_sync(FULL, v, o);
        int   ot = __shfl_xor_sync(FULL, tag, o);
        if (ov < v || (ov == v && ot < tag)) { v = ov; tag = ot; }
    }

    // psi = winning column / ||column||   (phase normalization cancels)
    float sc = rsqrtf(v);
    if (g == (tag >> 1)) {
        #pragma unroll
        for (int r = 0; r < 4; r++) {
            float2 cv = (tag & 1) ? B[r] : T[r];
            spsi[w][r * 4 + rl] = make_float2(cv.x * sc, cv.y * sc);
        }
    }
    __syncwarp();

    // t = sum_k psi_k
    float2 psi = (lane < 16) ? spsi[w][lane] : make_float2(0.f, 0.f);
    float2 tsum = psi;
    #pragma unroll
    for (int o = 16; o > 0; o >>= 1) {
        tsum.x += __shfl_xor_sync(FULL, tsum.x, o);
        tsum.y += __shfl_xor_sync(FULL, tsum.y, o);
    }

    // lane == d : u_d = r_d . psi ; v_d = r2_d . psi
    float2 u  = make_float2(0.f, 0.f);
    float2 v2 = make_float2(0.f, 0.f);
    #pragma unroll
    for (int j2 = 0; j2 < 16; j2++) {
        float2 pj = spsi[w][j2];
        float2 rr = g_r[lane * 16 + j2];
        u.x += rr.x * pj.x - rr.y * pj.y;
        u.y += rr.x * pj.y + rr.y * pj.x;
        float2 r2 = g_r2[lane * 16 + j2];
        v2.x += r2.x * pj.x - r2.y * pj.y;
        v2.y += r2.x * pj.y + r2.y * pj.x;
    }
    float pos = u.x  * tsum.x + u.y  * tsum.y;   // Re(u * conj(t))
    float e2  = v2.x * tsum.x + v2.y * tsum.y;
    float dlt = pos - x;
    float contrib = dlt * dlt + LAM * (e2 - pos * pos);

    #pragma unroll
    for (int o = 16; o > 0; o >>= 1)
        contrib += __shfl_xor_sync(FULL, contrib, o);

    if (lane == 0) {
        atomicAdd(&g_acc, (double)contrib);
        __threadfence();
        unsigned int t = atomicAdd(&g_cnt, 1u);
        if (t == (unsigned)(NTOT - 1)) {
            double total = atomicAdd(&g_acc, 0.0);   // coherent read of final sum
            out[0] = (float)(total * (1.0 / (double)NTOT));
        }
    }
}

extern "C" void kernel_launch(void* const* d_in, const int* in_sizes, int n_in,
                              void* d_out, int out_size) {
    const float* Ar = (const float*)d_in[0];
    const float* Ai = (const float*)d_in[1];
    const float* X  = (const float*)d_in[2];
    float* out = (float*)d_out;

    precompute_kernel<<<DD + 1, 256>>>(Ar, Ai);
    solve_kernel<<<NTOT / WARPS_PER_BLK, WARPS_PER_BLK * 32>>>(X, out);
}

// round 6
// speedup vs baseline: 1.7422x; 1.7422x over previous
#include <cuda_runtime.h>
#include <math.h>

#define DD     32
#define DIMN   16
#define NTOT   4096
#define EPSV   1e-5f
#define LAM    0.1f
#define NSWEEP 5
#define WARPS_PER_BLK 4

// ---------------- scratch (device globals: no allocation allowed) -----------
__device__ float2 g_G[DIMN * DIMN];            // sum_d A_d A_d^H
__device__ float2 g_S[DD * DIMN * DIMN];       // A_d + A_d^H
__device__ float2 g_r[DD * DIMN];              // column sums of A_d
__device__ float2 g_r2[DD * DIMN];             // column sums of A_d @ A_d
__device__ double g_acc;
__device__ unsigned int g_cnt;

__device__ __forceinline__ float frcp(float a) {
    float r; asm("rcp.approx.f32 %0,%1;" : "=f"(r) : "f"(a)); return r;
}

// ---------------- kernel -1: zero accumulators ------------------------------
__global__ void zero_kernel() {
    int t = threadIdx.x;
    g_G[t] = make_float2(0.f, 0.f);
    if (t == 0) { g_acc = 0.0; g_cnt = 0u; }
}

// ---------------- kernel 0: constants from A (one block per d, atomic G) ----
__global__ void precompute_kernel(const float* __restrict__ Ar,
                                  const float* __restrict__ Ai) {
    __shared__ float2 sr[DIMN];
    const int d = blockIdx.x;
    const int t = threadIdx.x;          // 256 threads, one per (i,j)
    const int i = t >> 4, j = t & 15;
    const float* ar = Ar + d * 256;
    const float* ai = Ai + d * 256;

    // S_d = A_d + A_d^H
    float arij = ar[i * 16 + j], aiij = ai[i * 16 + j];
    float arji = ar[j * 16 + i], aiji = ai[j * 16 + i];
    g_S[d * 256 + t] = make_float2(arij + arji, aiij - aiji);

    // partial G: G[i][j] += sum_k A[i,k] conj(A[j,k])
    float gx = 0.f, gy = 0.f;
    #pragma unroll
    for (int k = 0; k < 16; k++) {
        float axr = ar[i * 16 + k], axi = ai[i * 16 + k];
        float bxr = ar[j * 16 + k], bxi = ai[j * 16 + k];
        gx += axr * bxr + axi * bxi;
        gy += axi * bxr - axr * bxi;
    }
    atomicAdd(&g_G[t].x, gx);
    atomicAdd(&g_G[t].y, gy);

    // r_d[j] = sum_i A_d[i,j]
    if (t < 16) {
        float2 s = make_float2(0.f, 0.f);
        #pragma unroll
        for (int ii = 0; ii < 16; ii++) {
            s.x += ar[ii * 16 + t];
            s.y += ai[ii * 16 + t];
        }
        sr[t] = s;
        g_r[d * 16 + t] = s;
    }
    __syncthreads();
    // r2_d[j] = sum_k r_d[k] * A_d[k,j]
    if (t < 16) {
        float2 s = make_float2(0.f, 0.f);
        #pragma unroll
        for (int k = 0; k < 16; k++) {
            float2 rk = sr[k];
            float axr = ar[k * 16 + t], axi = ai[k * 16 + t];
            s.x += rk.x * axr - rk.y * axi;
            s.y += rk.x * axi + rk.y * axr;
        }
        g_r2[d * 16 + t] = s;
    }
}

// ---------------- kernel 1: build H, one-sided Jacobi in registers ----------
__global__ void __launch_bounds__(WARPS_PER_BLK * 32)
solve_kernel(const float* __restrict__ X, float* __restrict__ out) {
    __shared__ float2 sH[WARPS_PER_BLK][DIMN * 17];   // build/transpose buffer
    __shared__ float2 spsi[WARPS_PER_BLK][DIMN];

    const int w    = threadIdx.x >> 5;
    const int lane = threadIdx.x & 31;
    const int n    = blockIdx.x * WARPS_PER_BLK + w;
    const unsigned FULL = 0xffffffffu;

    float2* H = sH[w];

    // ---- load x_n, ||x||^2 ----
    float x = X[n * DD + lane];
    float sx2 = x * x;
    #pragma unroll
    for (int o = 16; o > 0; o >>= 1) sx2 += __shfl_xor_sync(FULL, sx2, o);

    // ---- H = 0.5*G - 0.5*sum_d x_d S_d + (eps + 0.5*||x||^2) I ----
    {
        float2 acc[8];
        #pragma unroll
        for (int m = 0; m < 8; m++) {
            float2 g = g_G[m * 32 + lane];
            acc[m] = make_float2(0.5f * g.x, 0.5f * g.y);
        }
        #pragma unroll
        for (int d = 0; d < DD; d++) {
            float h = 0.5f * __shfl_sync(FULL, x, d);
            #pragma unroll
            for (int m = 0; m < 8; m++) {
                float2 s = g_S[d * 256 + m * 32 + lane];
                acc[m].x -= h * s.x;
                acc[m].y -= h * s.y;
            }
        }
        #pragma unroll
        for (int m = 0; m < 8; m++) {
            int e = m * 32 + lane;
            int i = e >> 4, j = e & 15;
            if (i == j) acc[m].x += EPSV + 0.5f * sx2;
            H[i * 17 + j] = acc[m];
        }
    }
    __syncwarp();

    // ---- register layout: group g = lane>>2 holds columns (2g, 2g+1);
    //      lane rl = lane&3 holds rows {4r+rl} ----
    const int g  = lane >> 2;
    const int rl = lane & 3;

    float2 T[4], B[4];
    #pragma unroll
    for (int r = 0; r < 4; r++) {
        T[r] = H[(r * 4 + rl) * 17 + 2 * g];
        B[r] = H[(r * 4 + rl) * 17 + 2 * g + 1];
    }

    // ---- one-sided Jacobi: 15 rounds/sweep (round-robin), registers only ----
    for (int it = 0; it < NSWEEP * 15; it++) {
        // Gram: (|B|^2 - |T|^2) and conj(T).B
        float df = 0.f, bx = 0.f, by = 0.f;
        #pragma unroll
        for (int r = 0; r < 4; r++) {
            df += (B[r].x * B[r].x + B[r].y * B[r].y)
                - (T[r].x * T[r].x + T[r].y * T[r].y);
            bx += T[r].x * B[r].x + T[r].y * B[r].y;   // Re conj(T).B
            by += T[r].x * B[r].y - T[r].y * B[r].x;   // Im conj(T).B
        }
        #pragma unroll
        for (int o = 1; o <= 2; o <<= 1) {
            df += __shfl_xor_sync(FULL, df, o);
            bx += __shfl_xor_sync(FULL, bx, o);
            by += __shfl_xor_sync(FULL, by, o);
        }

        // rotation params — division/sqrt-free fast path (MUFU only)
        float ab2 = bx * bx + by * by;
        float c = 1.f, wx = 0.f, wy = 0.f;
        if (ab2 > 1e-28f) {
            float rab = rsqrtf(ab2);                 // 1/|b|
            float tau = 0.5f * df * rab;
            float t2  = tau * tau + 1.f;
            float sq  = t2 * rsqrtf(t2);             // sqrt(t2)
            float den = fabsf(tau) + sq;
            float tt  = ((tau >= 0.f) ? 1.f : -1.f) * frcp(den);
            c = rsqrtf(tt * tt + 1.f);
            float inv = tt * c * rab;                // s/|b|
            wx = bx * inv; wy = by * inv;
        }

        // column update + fused round-robin permutation (circle method)
        #pragma unroll
        for (int r = 0; r < 4; r++) {
            float tx = T[r].x, ty = T[r].y;
            float bxr = B[r].x, byr = B[r].y;
            float ntx = c * tx - (wx * bxr + wy * byr);
            float nty = c * ty - (wx * byr - wy * bxr);
            float nbx = (wx * tx - wy * ty) + c * bxr;
            float nby = (wx * ty + wy * tx) + c * byr;

            float selx = (g == 0) ? nbx : ntx;
            float sely = (g == 0) ? nby : nty;
            float upx = __shfl_sync(FULL, selx, lane - 4);
            float upy = __shfl_sync(FULL, sely, lane - 4);
            float dnx = __shfl_sync(FULL, nbx, lane + 4);
            float dny = __shfl_sync(FULL, nby, lane + 4);

            T[r] = (g == 0) ? make_float2(ntx, nty) : make_float2(upx, upy);
            B[r] = (g == 7) ? make_float2(ntx, nty) : make_float2(dnx, dny);
        }
    }

    // ---- column norms, pick minimum (= min eigenvalue's column) ----
    float nT = 0.f, nB = 0.f;
    #pragma unroll
    for (int r = 0; r < 4; r++) {
        nT += T[r].x * T[r].x + T[r].y * T[r].y;
        nB += B[r].x * B[r].x + B[r].y * B[r].y;
    }
    #pragma unroll
    for (int o = 1; o <= 2; o <<= 1) {
        nT += __shfl_xor_sync(FULL, nT, o);
        nB += __shfl_xor_sync(FULL, nB, o);
    }
    float v; int tag;
    if (nB < nT) { v = nB; tag = 2 * g + 1; } else { v = nT; tag = 2 * g; }
    #pragma unroll
    for (int o = 4; o <= 16; o <<= 1) {
        float ov = __shfl_xor_sync(FULL, v, o);
        int   ot = __shfl_xor_sync(FULL, tag, o);
        if (ov < v || (ov == v && ot < tag)) { v = ov; tag = ot; }
    }

    // psi = winning column / ||column||   (phase normalization cancels)
    float sc = rsqrtf(v);
    if (g == (tag >> 1)) {
        #pragma unroll
        for (int r = 0; r < 4; r++) {
            float2 cv = (tag & 1) ? B[r] : T[r];
            spsi[w][r * 4 + rl] = make_float2(cv.x * sc, cv.y * sc);
        }
    }
    __syncwarp();

    // t = sum_k psi_k
    float2 psi = (lane < 16) ? spsi[w][lane] : make_float2(0.f, 0.f);
    float2 tsum = psi;
    #pragma unroll
    for (int o = 16; o > 0; o >>= 1) {
        tsum.x += __shfl_xor_sync(FULL, tsum.x, o);
        tsum.y += __shfl_xor_sync(FULL, tsum.y, o);
    }

    // lane == d : u_d = r_d . psi ; v_d = r2_d . psi
    float2 u  = make_float2(0.f, 0.f);
    float2 v2 = make_float2(0.f, 0.f);
    #pragma unroll
    for (int j2 = 0; j2 < 16; j2++) {
        float2 pj = spsi[w][j2];
        float2 rr = g_r[lane * 16 + j2];
        u.x += rr.x * pj.x - rr.y * pj.y;
        u.y += rr.x * pj.y + rr.y * pj.x;
        float2 r2 = g_r2[lane * 16 + j2];
        v2.x += r2.x * pj.x - r2.y * pj.y;
        v2.y += r2.x * pj.y + r2.y * pj.x;
    }
    float pos = u.x  * tsum.x + u.y  * tsum.y;   // Re(u * conj(t))
    float e2  = v2.x * tsum.x + v2.y * tsum.y;
    float dlt = pos - x;
    float contrib = dlt * dlt + LAM * (e2 - pos * pos);

    #pragma unroll
    for (int o = 16; o > 0; o >>= 1)
        contrib += __shfl_xor_sync(FULL, contrib, o);

    if (lane == 0) {
        atomicAdd(&g_acc, (double)contrib);
        __threadfence();
        unsigned int t = atomicAdd(&g_cnt, 1u);
        if (t == (unsigned)(NTOT - 1)) {
            double total = atomicAdd(&g_acc, 0.0);   // coherent read of final sum
            out[0] = (float)(total * (1.0 / (double)NTOT));
        }
    }
}

extern "C" void kernel_launch(void* const* d_in, const int* in_sizes, int n_in,
                              void* d_out, int out_size) {
    const float* Ar = (const float*)d_in[0];
    const float* Ai = (const float*)d_in[1];
    const float* X  = (const float*)d_in[2];
    float* out = (float*)d_out;

    zero_kernel<<<1, 256>>>();
    precompute_kernel<<<DD, 256>>>(Ar, Ai);
    solve_kernel<<<NTOT / WARPS_PER_BLK, WARPS_PER_BLK * 32>>>(X, out);
}

// round 7
// speedup vs baseline: 1.9477x; 1.1180x over previous
#include <cuda_runtime.h>
#include <math.h>

#define DD     32
#define DIMN   16
#define NTOT   4096
#define EPSV   1e-5f
#define LAM    0.1f
#define NSWEEP 4
#define WARPS_PER_BLK 4

// ---------------- scratch (device globals: no allocation allowed) -----------
// Zeroed members packed together so one cudaMemsetAsync covers all of them.
struct ZeroBlock {
    float2 G[DIMN * DIMN];   // sum_d A_d A_d^H (atomic accumulate)
    double acc;              // loss accumulator
    unsigned int cnt;        // completion ticket
};
__device__ ZeroBlock g_Z;
__device__ float2 g_S[DD * DIMN * DIMN];       // A_d + A_d^H
__device__ float2 g_r[DD * DIMN];              // column sums of A_d
__device__ float2 g_r2[DD * DIMN];             // column sums of A_d @ A_d

__device__ __forceinline__ float frcp(float a) {
    float r; asm("rcp.approx.f32 %0,%1;" : "=f"(r) : "f"(a)); return r;
}

// ---------------- kernel 0: constants from A (one block per d, atomic G) ----
__global__ void precompute_kernel(const float* __restrict__ Ar,
                                  const float* __restrict__ Ai) {
    __shared__ float2 sr[DIMN];
    const int d = blockIdx.x;
    const int t = threadIdx.x;          // 256 threads, one per (i,j)
    const int i = t >> 4, j = t & 15;
    const float* ar = Ar + d * 256;
    const float* ai = Ai + d * 256;

    // S_d = A_d + A_d^H
    float arij = ar[i * 16 + j], aiij = ai[i * 16 + j];
    float arji = ar[j * 16 + i], aiji = ai[j * 16 + i];
    g_S[d * 256 + t] = make_float2(arij + arji, aiij - aiji);

    // partial G: G[i][j] += sum_k A[i,k] conj(A[j,k])
    float gx = 0.f, gy = 0.f;
    #pragma unroll
    for (int k = 0; k < 16; k++) {
        float axr = ar[i * 16 + k], axi = ai[i * 16 + k];
        float bxr = ar[j * 16 + k], bxi = ai[j * 16 + k];
        gx += axr * bxr + axi * bxi;
        gy += axi * bxr - axr * bxi;
    }
    atomicAdd(&g_Z.G[t].x, gx);
    atomicAdd(&g_Z.G[t].y, gy);

    // r_d[j] = sum_i A_d[i,j]
    if (t < 16) {
        float2 s = make_float2(0.f, 0.f);
        #pragma unroll
        for (int ii = 0; ii < 16; ii++) {
            s.x += ar[ii * 16 + t];
            s.y += ai[ii * 16 + t];
        }
        sr[t] = s;
        g_r[d * 16 + t] = s;
    }
    __syncthreads();
    // r2_d[j] = sum_k r_d[k] * A_d[k,j]
    if (t < 16) {
        float2 s = make_float2(0.f, 0.f);
        #pragma unroll
        for (int k = 0; k < 16; k++) {
            float2 rk = sr[k];
            float axr = ar[k * 16 + t], axi = ai[k * 16 + t];
            s.x += rk.x * axr - rk.y * axi;
            s.y += rk.x * axi + rk.y * axr;
        }
        g_r2[d * 16 + t] = s;
    }
}

// ---------------- kernel 1: build H, one-sided Jacobi in registers ----------
__global__ void __launch_bounds__(WARPS_PER_BLK * 32)
solve_kernel(const float* __restrict__ X, float* __restrict__ out) {
    __shared__ float2 sH[WARPS_PER_BLK][DIMN * 17];   // build/transpose buffer
    __shared__ float2 spsi[WARPS_PER_BLK][DIMN];

    const int w    = threadIdx.x >> 5;
    const int lane = threadIdx.x & 31;
    const int n    = blockIdx.x * WARPS_PER_BLK + w;
    const unsigned FULL = 0xffffffffu;

    float2* H = sH[w];

    // ---- load x_n, ||x||^2 ----
    float x = X[n * DD + lane];
    float sx2 = x * x;
    #pragma unroll
    for (int o = 16; o > 0; o >>= 1) sx2 += __shfl_xor_sync(FULL, sx2, o);

    // ---- H = 0.5*G - 0.5*sum_d x_d S_d + (eps + 0.5*||x||^2) I ----
    {
        float2 acc[8];
        #pragma unroll
        for (int m = 0; m < 8; m++) {
            float2 g = g_Z.G[m * 32 + lane];
            acc[m] = make_float2(0.5f * g.x, 0.5f * g.y);
        }
        #pragma unroll
        for (int d = 0; d < DD; d++) {
            float h = 0.5f * __shfl_sync(FULL, x, d);
            #pragma unroll
            for (int m = 0; m < 8; m++) {
                float2 s = g_S[d * 256 + m * 32 + lane];
                acc[m].x -= h * s.x;
                acc[m].y -= h * s.y;
            }
        }
        #pragma unroll
        for (int m = 0; m < 8; m++) {
            int e = m * 32 + lane;
            int i = e >> 4, j = e & 15;
            if (i == j) acc[m].x += EPSV + 0.5f * sx2;
            H[i * 17 + j] = acc[m];
        }
    }
    __syncwarp();

    // ---- register layout: group g = lane>>2 holds columns (2g, 2g+1);
    //      lane rl = lane&3 holds rows {4r+rl} ----
    const int g  = lane >> 2;
    const int rl = lane & 3;

    float2 T[4], B[4];
    #pragma unroll
    for (int r = 0; r < 4; r++) {
        T[r] = H[(r * 4 + rl) * 17 + 2 * g];
        B[r] = H[(r * 4 + rl) * 17 + 2 * g + 1];
    }

    // ---- one-sided Jacobi: 15 rounds/sweep (round-robin), registers only ----
    const int NROUND = NSWEEP * 15;
    for (int it = 0; it < NROUND; it++) {
        // Gram: (|B|^2 - |T|^2) and conj(T).B
        float df = 0.f, bx = 0.f, by = 0.f;
        #pragma unroll
        for (int r = 0; r < 4; r++) {
            df += (B[r].x * B[r].x + B[r].y * B[r].y)
                - (T[r].x * T[r].x + T[r].y * T[r].y);
            bx += T[r].x * B[r].x + T[r].y * B[r].y;   // Re conj(T).B
            by += T[r].x * B[r].y - T[r].y * B[r].x;   // Im conj(T).B
        }
        #pragma unroll
        for (int o = 1; o <= 2; o <<= 1) {
            df += __shfl_xor_sync(FULL, df, o);
            bx += __shfl_xor_sync(FULL, bx, o);
            by += __shfl_xor_sync(FULL, by, o);
        }

        // rotation params — division/sqrt-free fast path (MUFU only)
        float ab2 = bx * bx + by * by;
        float c = 1.f, wx = 0.f, wy = 0.f;
        if (ab2 > 1e-28f) {
            float rab = rsqrtf(ab2);                 // 1/|b|
            float tau = 0.5f * df * rab;
            float t2  = tau * tau + 1.f;
            float sq  = t2 * rsqrtf(t2);             // sqrt(t2)
            float den = fabsf(tau) + sq;
            float tt  = ((tau >= 0.f) ? 1.f : -1.f) * frcp(den);
            c = rsqrtf(tt * tt + 1.f);
            float inv = tt * c * rab;                // s/|b|
            wx = bx * inv; wy = by * inv;
        }

        const bool last = (it == NROUND - 1);

        // column update + fused round-robin permutation (circle method)
        #pragma unroll
        for (int r = 0; r < 4; r++) {
            float tx = T[r].x, ty = T[r].y;
            float bxr = B[r].x, byr = B[r].y;
            float ntx = c * tx - (wx * bxr + wy * byr);
            float nty = c * ty - (wx * byr - wy * bxr);
            float nbx = (wx * tx - wy * ty) + c * bxr;
            float nby = (wx * ty + wy * tx) + c * byr;

            if (last) {   // no permutation needed after the final rotation
                T[r] = make_float2(ntx, nty);
                B[r] = make_float2(nbx, nby);
            } else {
                float selx = (g == 0) ? nbx : ntx;
                float sely = (g == 0) ? nby : nty;
                float upx = __shfl_sync(FULL, selx, lane - 4);
                float upy = __shfl_sync(FULL, sely, lane - 4);
                float dnx = __shfl_sync(FULL, nbx, lane + 4);
                float dny = __shfl_sync(FULL, nby, lane + 4);

                T[r] = (g == 0) ? make_float2(ntx, nty) : make_float2(upx, upy);
                B[r] = (g == 7) ? make_float2(ntx, nty) : make_float2(dnx, dny);
            }
        }
    }

    // ---- column norms, pick minimum (= min eigenvalue's column) ----
    float nT = 0.f, nB = 0.f;
    #pragma unroll
    for (int r = 0; r < 4; r++) {
        nT += T[r].x * T[r].x + T[r].y * T[r].y;
        nB += B[r].x * B[r].x + B[r].y * B[r].y;
    }
    #pragma unroll
    for (int o = 1; o <= 2; o <<= 1) {
        nT += __shfl_xor_sync(FULL, nT, o);
        nB += __shfl_xor_sync(FULL, nB, o);
    }
    float v; int tag;
    if (nB < nT) { v = nB; tag = 2 * g + 1; } else { v = nT; tag = 2 * g; }
    #pragma unroll
    for (int o = 4; o <= 16; o <<= 1) {
        float ov = __shfl_xor_sync(FULL, v, o);
        int   ot = __shfl_xor_sync(FULL, tag, o);
        if (ov < v || (ov == v && ot < tag)) { v = ov; tag = ot; }
    }

    // psi = winning column / ||column||   (phase normalization cancels)
    float sc = rsqrtf(v);
    if (g == (tag >> 1)) {
        #pragma unroll
        for (int r = 0; r < 4; r++) {
            float2 cv = (tag & 1) ? B[r] : T[r];
            spsi[w][r * 4 + rl] = make_float2(cv.x * sc, cv.y * sc);
        }
    }
    __syncwarp();

    // t = sum_k psi_k
    float2 psi = (lane < 16) ? spsi[w][lane] : make_float2(0.f, 0.f);
    float2 tsum = psi;
    #pragma unroll
    for (int o = 16; o > 0; o >>= 1) {
        tsum.x += __shfl_xor_sync(FULL, tsum.x, o);
        tsum.y += __shfl_xor_sync(FULL, tsum.y, o);
    }

    // lane == d : u_d = r_d . psi ; v_d = r2_d . psi
    float2 u  = make_float2(0.f, 0.f);
    float2 v2 = make_float2(0.f, 0.f);
    #pragma unroll
    for (int j2 = 0; j2 < 16; j2++) {
        float2 pj = spsi[w][j2];
        float2 rr = g_r[lane * 16 + j2];
        u.x += rr.x * pj.x - rr.y * pj.y;
        u.y += rr.x * pj.y + rr.y * pj.x;
        float2 r2 = g_r2[lane * 16 + j2];
        v2.x += r2.x * pj.x - r2.y * pj.y;
        v2.y += r2.x * pj.y + r2.y * pj.x;
    }
    float pos = u.x  * tsum.x + u.y  * tsum.y;   // Re(u * conj(t))
    float e2  = v2.x * tsum.x + v2.y * tsum.y;
    float dlt = pos - x;
    float contrib = dlt * dlt + LAM * (e2 - pos * pos);

    #pragma unroll
    for (int o = 16; o > 0; o >>= 1)
        contrib += __shfl_xor_sync(FULL, contrib, o);

    if (lane == 0) {
        atomicAdd(&g_Z.acc, (double)contrib);
        __threadfence();
        unsigned int t = atomicAdd(&g_Z.cnt, 1u);
        if (t == (unsigned)(NTOT - 1)) {
            double total = atomicAdd(&g_Z.acc, 0.0);   // coherent read of final sum
            out[0] = (float)(total * (1.0 / (double)NTOT));
        }
    }
}

extern "C" void kernel_launch(void* const* d_in, const int* in_sizes, int n_in,
                              void* d_out, int out_size) {
    const float* Ar = (const float*)d_in[0];
    const float* Ai = (const float*)d_in[1];
    const float* X  = (const float*)d_in[2];
    float* out = (float*)d_out;

    void* zptr = nullptr;
    cudaGetSymbolAddress(&zptr, g_Z);
    cudaMemsetAsync(zptr, 0, sizeof(ZeroBlock), 0);   // zero G/acc/cnt in one node

    precompute_kernel<<<DD, 256>>>(Ar, Ai);
    solve_kernel<<<NTOT / WARPS_PER_BLK, WARPS_PER_BLK * 32>>>(X, out);
}

// round 8
// speedup vs baseline: 1.9884x; 1.0209x over previous
#include <cuda_runtime.h>
#include <math.h>

#define DD     32
#define DIMN   16
#define NTOT   4096
#define EPSV   1e-5f
#define LAM    0.1f
#define NSWEEP 4
#define WPB    2       // warps per block
#define MPW    2       // matrices per warp (ILP)

// ---------------- scratch (device globals: no allocation allowed) -----------
struct ZeroBlock {
    float2 G[DIMN * DIMN];   // sum_d A_d A_d^H (atomic accumulate)
    double acc;              // loss accumulator
    unsigned int cnt;        // completion ticket
};
__device__ ZeroBlock g_Z;
__device__ float2 g_S[DD * DIMN * DIMN];       // A_d + A_d^H
__device__ float2 g_r[DD * DIMN];              // column sums of A_d
__device__ float2 g_r2[DD * DIMN];             // column sums of A_d @ A_d

__device__ __forceinline__ float frcp(float a) {
    float r; asm("rcp.approx.f32 %0,%1;" : "=f"(r) : "f"(a)); return r;
}

// ---------------- kernel 0: constants from A (one block per d, atomic G) ----
__global__ void precompute_kernel(const float* __restrict__ Ar,
                                  const float* __restrict__ Ai) {
    __shared__ float2 sr[DIMN];
    const int d = blockIdx.x;
    const int t = threadIdx.x;          // 256 threads, one per (i,j)
    const int i = t >> 4, j = t & 15;
    const float* ar = Ar + d * 256;
    const float* ai = Ai + d * 256;

    float arij = ar[i * 16 + j], aiij = ai[i * 16 + j];
    float arji = ar[j * 16 + i], aiji = ai[j * 16 + i];
    g_S[d * 256 + t] = make_float2(arij + arji, aiij - aiji);

    float gx = 0.f, gy = 0.f;
    #pragma unroll
    for (int k = 0; k < 16; k++) {
        float axr = ar[i * 16 + k], axi = ai[i * 16 + k];
        float bxr = ar[j * 16 + k], bxi = ai[j * 16 + k];
        gx += axr * bxr + axi * bxi;
        gy += axi * bxr - axr * bxi;
    }
    atomicAdd(&g_Z.G[t].x, gx);
    atomicAdd(&g_Z.G[t].y, gy);

    if (t < 16) {
        float2 s = make_float2(0.f, 0.f);
        #pragma unroll
        for (int ii = 0; ii < 16; ii++) {
            s.x += ar[ii * 16 + t];
            s.y += ai[ii * 16 + t];
        }
        sr[t] = s;
        g_r[d * 16 + t] = s;
    }
    __syncthreads();
    if (t < 16) {
        float2 s = make_float2(0.f, 0.f);
        #pragma unroll
        for (int k = 0; k < 16; k++) {
            float2 rk = sr[k];
            float axr = ar[k * 16 + t], axi = ai[k * 16 + t];
            s.x += rk.x * axr - rk.y * axi;
            s.y += rk.x * axi + rk.y * axr;
        }
        g_r2[d * 16 + t] = s;
    }
}

// ---------------- kernel 1: build H, one-sided Jacobi, 2 matrices/warp ------
__global__ void __launch_bounds__(WPB * 32)
solve_kernel(const float* __restrict__ X, float* __restrict__ out) {
    __shared__ float2 sH[WPB][DIMN * 17];        // build/transpose buffer
    __shared__ float2 spsi[WPB][MPW][DIMN];

    const int w     = threadIdx.x >> 5;
    const int lane  = threadIdx.x & 31;
    const int nbase = (blockIdx.x * WPB + w) * MPW;
    const unsigned FULL = 0xffffffffu;

    float2* H = sH[w];
    const int g  = lane >> 2;
    const int rl = lane & 3;

    float2 T[MPW][4], B[MPW][4];
    float  x[MPW], nrmT[MPW], nrmB[MPW];

    // ---- build both H matrices (sequential through the shared buffer) ----
    #pragma unroll
    for (int m = 0; m < MPW; m++) {
        x[m] = X[(nbase + m) * DD + lane];
        float sx2 = x[m] * x[m];
        #pragma unroll
        for (int o = 16; o > 0; o >>= 1) sx2 += __shfl_xor_sync(FULL, sx2, o);

        float2 acc[8];
        #pragma unroll
        for (int mm = 0; mm < 8; mm++) {
            float2 gg = g_Z.G[mm * 32 + lane];
            acc[mm] = make_float2(0.5f * gg.x, 0.5f * gg.y);
        }
        #pragma unroll
        for (int d = 0; d < DD; d++) {
            float h = 0.5f * __shfl_sync(FULL, x[m], d);
            #pragma unroll
            for (int mm = 0; mm < 8; mm++) {
                float2 s = g_S[d * 256 + mm * 32 + lane];
                acc[mm].x -= h * s.x;
                acc[mm].y -= h * s.y;
            }
        }
        #pragma unroll
        for (int mm = 0; mm < 8; mm++) {
            int e = mm * 32 + lane;
            int i = e >> 4, j = e & 15;
            if (i == j) acc[mm].x += EPSV + 0.5f * sx2;
            H[i * 17 + j] = acc[mm];
        }
        __syncwarp();
        #pragma unroll
        for (int r = 0; r < 4; r++) {
            T[m][r] = H[(r * 4 + rl) * 17 + 2 * g];
            B[m][r] = H[(r * 4 + rl) * 17 + 2 * g + 1];
        }
        __syncwarp();   // buffer reused by next matrix

        // exact initial column norms
        float a = 0.f, d0 = 0.f;
        #pragma unroll
        for (int r = 0; r < 4; r++) {
            a  += T[m][r].x * T[m][r].x + T[m][r].y * T[m][r].y;
            d0 += B[m][r].x * B[m][r].x + B[m][r].y * B[m][r].y;
        }
        #pragma unroll
        for (int o = 1; o <= 2; o <<= 1) {
            a  += __shfl_xor_sync(FULL, a,  o);
            d0 += __shfl_xor_sync(FULL, d0, o);
        }
        nrmT[m] = a; nrmB[m] = d0;
    }

    // ---- one-sided Jacobi, round-robin, tracked norms, 2-way ILP ----
    const int NROUND = NSWEEP * 15;
    for (int it = 0; it < NROUND; it++) {
        const bool last = (it == NROUND - 1);
        float c[MPW], wx[MPW], wy[MPW], a2[MPW], d2[MPW];

        // phase 1: Gram off-diagonal + rotation params (independent chains)
        #pragma unroll
        for (int m = 0; m < MPW; m++) {
            float bx = 0.f, by = 0.f;
            #pragma unroll
            for (int r = 0; r < 4; r++) {
                bx += T[m][r].x * B[m][r].x + T[m][r].y * B[m][r].y;
                by += T[m][r].x * B[m][r].y - T[m][r].y * B[m][r].x;
            }
            #pragma unroll
            for (int o = 1; o <= 2; o <<= 1) {
                bx += __shfl_xor_sync(FULL, bx, o);
                by += __shfl_xor_sync(FULL, by, o);
            }
            float df  = nrmB[m] - nrmT[m];
            float ab2 = bx * bx + by * by;
            float cc = 1.f, wxx = 0.f, wyy = 0.f, delta = 0.f;
            if (ab2 > 1e-28f) {
                float rab = rsqrtf(ab2);
                float ab  = ab2 * rab;
                float tau = 0.5f * df * rab;
                float t2  = tau * tau + 1.f;
                float sq  = t2 * rsqrtf(t2);
                float den = fabsf(tau) + sq;
                float tt  = ((tau >= 0.f) ? 1.f : -1.f) * frcp(den);
                cc  = rsqrtf(tt * tt + 1.f);
                float inv = tt * cc * rab;
                wxx = bx * inv; wyy = by * inv;
                delta = tt * ab;
            }
            c[m] = cc; wx[m] = wxx; wy[m] = wyy;
            a2[m] = nrmT[m] - delta;
            d2[m] = nrmB[m] + delta;
        }

        // phase 2: column update + fused permutation (independent chains)
        #pragma unroll
        for (int m = 0; m < MPW; m++) {
            #pragma unroll
            for (int r = 0; r < 4; r++) {
                float tx = T[m][r].x, ty = T[m][r].y;
                float bxr = B[m][r].x, byr = B[m][r].y;
                float ntx = c[m] * tx - (wx[m] * bxr + wy[m] * byr);
                float nty = c[m] * ty - (wx[m] * byr - wy[m] * bxr);
                float nbx = (wx[m] * tx - wy[m] * ty) + c[m] * bxr;
                float nby = (wx[m] * ty + wy[m] * tx) + c[m] * byr;

                if (last) {
                    T[m][r] = make_float2(ntx, nty);
                    B[m][r] = make_float2(nbx, nby);
                } else {
                    float selx = (g == 0) ? nbx : ntx;
                    float sely = (g == 0) ? nby : nty;
                    float upx = __shfl_sync(FULL, selx, lane - 4);
                    float upy = __shfl_sync(FULL, sely, lane - 4);
                    float dnx = __shfl_sync(FULL, nbx, lane + 4);
                    float dny = __shfl_sync(FULL, nby, lane + 4);
                    T[m][r] = (g == 0) ? make_float2(ntx, nty) : make_float2(upx, upy);
                    B[m][r] = (g == 7) ? make_float2(ntx, nty) : make_float2(dnx, dny);
                }
            }
            if (last) {
                nrmT[m] = a2[m]; nrmB[m] = d2[m];
            } else {
                float selN = (g == 0) ? d2[m] : a2[m];
                float upN  = __shfl_sync(FULL, selN, lane - 4);
                float dnN  = __shfl_sync(FULL, d2[m], lane + 4);
                nrmT[m] = (g == 0) ? a2[m] : upN;
                nrmB[m] = (g == 7) ? a2[m] : dnN;
            }
        }
    }

    // ---- epilogue: exact norms, min selection, psi, loss ----
    float vmin[MPW]; int tag[MPW];
    #pragma unroll
    for (int m = 0; m < MPW; m++) {
        float nT = 0.f, nB = 0.f;
        #pragma unroll
        for (int r = 0; r < 4; r++) {
            nT += T[m][r].x * T[m][r].x + T[m][r].y * T[m][r].y;
            nB += B[m][r].x * B[m][r].x + B[m][r].y * B[m][r].y;
        }
        #pragma unroll
        for (int o = 1; o <= 2; o <<= 1) {
            nT += __shfl_xor_sync(FULL, nT, o);
            nB += __shfl_xor_sync(FULL, nB, o);
        }
        float v; int tg;
        if (nB < nT) { v = nB; tg = 2 * g + 1; } else { v = nT; tg = 2 * g; }
        #pragma unroll
        for (int o = 4; o <= 16; o <<= 1) {
            float ov = __shfl_xor_sync(FULL, v, o);
            int   ot = __shfl_xor_sync(FULL, tg, o);
            if (ov < v || (ov == v && ot < tg)) { v = ov; tg = ot; }
        }
        vmin[m] = v; tag[m] = tg;

        float sc = rsqrtf(v);
        if (g == (tg >> 1)) {
            #pragma unroll
            for (int r = 0; r < 4; r++) {
                float2 cv = (tg & 1) ? B[m][r] : T[m][r];
                spsi[w][m][r * 4 + rl] = make_float2(cv.x * sc, cv.y * sc);
            }
        }
    }
    __syncwarp();

    float contrib = 0.f;
    #pragma unroll
    for (int m = 0; m < MPW; m++) {
        float2 psi = (lane < 16) ? spsi[w][m][lane] : make_float2(0.f, 0.f);
        float2 tsum = psi;
        #pragma unroll
        for (int o = 16; o > 0; o >>= 1) {
            tsum.x += __shfl_xor_sync(FULL, tsum.x, o);
            tsum.y += __shfl_xor_sync(FULL, tsum.y, o);
        }

        float2 u  = make_float2(0.f, 0.f);
        float2 v2 = make_float2(0.f, 0.f);
        #pragma unroll
        for (int j2 = 0; j2 < 16; j2++) {
            float2 pj = spsi[w][m][j2];
            float2 rr = g_r[lane * 16 + j2];
            u.x += rr.x * pj.x - rr.y * pj.y;
            u.y += rr.x * pj.y + rr.y * pj.x;
            float2 r2 = g_r2[lane * 16 + j2];
            v2.x += r2.x * pj.x - r2.y * pj.y;
            v2.y += r2.x * pj.y + r2.y * pj.x;
        }
        float pos = u.x  * tsum.x + u.y  * tsum.y;   // Re(u * conj(t))
        float e2  = v2.x * tsum.x + v2.y * tsum.y;
        float dlt = pos - x[m];
        contrib += dlt * dlt + LAM * (e2 - pos * pos);
    }

    #pragma unroll
    for (int o = 16; o > 0; o >>= 1)
        contrib += __shfl_xor_sync(FULL, contrib, o);

    if (lane == 0) {
        atomicAdd(&g_Z.acc, (double)contrib);
        __threadfence();
        unsigned int t = atomicAdd(&g_Z.cnt, 1u);
        if (t == (unsigned)(NTOT / MPW - 1)) {
            double total = atomicAdd(&g_Z.acc, 0.0);   // coherent final read
            out[0] = (float)(total * (1.0 / (double)NTOT));
        }
    }
}

extern "C" void kernel_launch(void* const* d_in, const int* in_sizes, int n_in,
                              void* d_out, int out_size) {
    const float* Ar = (const float*)d_in[0];
    const float* Ai = (const float*)d_in[1];
    const float* X  = (const float*)d_in[2];
    float* out = (float*)d_out;

    void* zptr = nullptr;
    cudaGetSymbolAddress(&zptr, g_Z);
    cudaMemsetAsync(zptr, 0, sizeof(ZeroBlock), 0);

    precompute_kernel<<<DD, 256>>>(Ar, Ai);
    solve_kernel<<<NTOT / (WPB * MPW), WPB * 32>>>(X, out);
}

// round 9
// speedup vs baseline: 2.2102x; 1.1116x over previous
#include <cuda_runtime.h>
#include <math.h>

#define DD     32
#define DIMN   16
#define NTOT   4096
#define EPSV   1e-5f
#define LAM    0.1f
#define NSWEEP 4
#define WPB    2       // warps per block; each warp solves 2 matrices (lane halves)

// ---------------- scratch (device globals: no allocation allowed) -----------
struct ZeroBlock {
    float2 G[DIMN * DIMN];   // sum_d A_d A_d^H (atomic accumulate)
    double acc;              // loss accumulator
    unsigned int cnt;        // completion ticket
};
__device__ ZeroBlock g_Z;
__device__ float2 g_S[DD * DIMN * DIMN];       // A_d + A_d^H
__device__ float2 g_r[DD * DIMN];              // column sums of A_d
__device__ float2 g_r2[DD * DIMN];             // column sums of A_d @ A_d

__device__ __forceinline__ float frcp(float a) {
    float r; asm("rcp.approx.f32 %0,%1;" : "=f"(r) : "f"(a)); return r;
}

// ---------------- kernel 0: constants from A (one block per d, atomic G) ----
__global__ void precompute_kernel(const float* __restrict__ Ar,
                                  const float* __restrict__ Ai) {
    __shared__ float2 sr[DIMN];
    const int d = blockIdx.x;
    const int t = threadIdx.x;          // 256 threads, one per (i,j)
    const int i = t >> 4, j = t & 15;
    const float* ar = Ar + d * 256;
    const float* ai = Ai + d * 256;

    float arij = ar[i * 16 + j], aiij = ai[i * 16 + j];
    float arji = ar[j * 16 + i], aiji = ai[j * 16 + i];
    g_S[d * 256 + t] = make_float2(arij + arji, aiij - aiji);

    float gx = 0.f, gy = 0.f;
    #pragma unroll
    for (int k = 0; k < 16; k++) {
        float axr = ar[i * 16 + k], axi = ai[i * 16 + k];
        float bxr = ar[j * 16 + k], bxi = ai[j * 16 + k];
        gx += axr * bxr + axi * bxi;
        gy += axi * bxr - axr * bxi;
    }
    atomicAdd(&g_Z.G[t].x, gx);
    atomicAdd(&g_Z.G[t].y, gy);

    if (t < 16) {
        float2 s = make_float2(0.f, 0.f);
        #pragma unroll
        for (int ii = 0; ii < 16; ii++) {
            s.x += ar[ii * 16 + t];
            s.y += ai[ii * 16 + t];
        }
        sr[t] = s;
        g_r[d * 16 + t] = s;
    }
    __syncthreads();
    if (t < 16) {
        float2 s = make_float2(0.f, 0.f);
        #pragma unroll
        for (int k = 0; k < 16; k++) {
            float2 rk = sr[k];
            float axr = ar[k * 16 + t], axi = ai[k * 16 + t];
            s.x += rk.x * axr - rk.y * axi;
            s.y += rk.x * axi + rk.y * axr;
        }
        g_r2[d * 16 + t] = s;
    }
}

// ---------------- kernel 1: split-warp Jacobi, 2 matrices per warp ----------
// Matrix (lane>>4) lives in that 16-lane half: 8 column-pairs x 2 lanes,
// each lane holds rows {2r + (hl&1)} of columns {2*g2, 2*g2+1}.
__global__ void __launch_bounds__(WPB * 32)
solve_kernel(const float* __restrict__ X, float* __restrict__ out) {
    __shared__ float2 sH[WPB][DIMN * 17];        // build/transpose buffer
    __shared__ float2 spsi[WPB][2][DIMN];

    const int w     = threadIdx.x >> 5;
    const int lane  = threadIdx.x & 31;
    const int nbase = (blockIdx.x * WPB + w) * 2;
    const unsigned FULL = 0xffffffffu;

    const int m   = lane >> 4;       // which matrix of the pair
    const int hl  = lane & 15;       // lane within half
    const int g2  = hl >> 1;         // column-pair group 0..7
    const int rl2 = hl & 1;          // row parity within group

    float2* H = sH[w];
    float2 T[8], B[8];
    float  x2[2];
    float  nrmT, nrmB;

    // ---- build both H matrices (full warp per matrix, buffer reused) ----
    x2[0] = X[nbase * DD + lane];
    x2[1] = X[(nbase + 1) * DD + lane];

    #pragma unroll
    for (int mm = 0; mm < 2; mm++) {
        float sx2 = x2[mm] * x2[mm];
        #pragma unroll
        for (int o = 16; o > 0; o >>= 1) sx2 += __shfl_xor_sync(FULL, sx2, o);

        float2 acc[8];
        #pragma unroll
        for (int k = 0; k < 8; k++) {
            float2 gg = g_Z.G[k * 32 + lane];
            acc[k] = make_float2(0.5f * gg.x, 0.5f * gg.y);
        }
        #pragma unroll
        for (int d = 0; d < DD; d++) {
            float h = 0.5f * __shfl_sync(FULL, x2[mm], d);
            #pragma unroll
            for (int k = 0; k < 8; k++) {
                float2 s = g_S[d * 256 + k * 32 + lane];
                acc[k].x -= h * s.x;
                acc[k].y -= h * s.y;
            }
        }
        #pragma unroll
        for (int k = 0; k < 8; k++) {
            int e = k * 32 + lane;
            int i = e >> 4, j = e & 15;
            if (i == j) acc[k].x += EPSV + 0.5f * sx2;
            H[i * 17 + j] = acc[k];
        }
        __syncwarp();
        if (m == mm) {
            #pragma unroll
            for (int r = 0; r < 8; r++) {
                T[r] = H[(2 * r + rl2) * 17 + 2 * g2];
                B[r] = H[(2 * r + rl2) * 17 + 2 * g2 + 1];
            }
        }
        __syncwarp();
    }

    // exact initial column norms (pair = 2 lanes, butterfly xor 1)
    {
        float a = 0.f, d0 = 0.f;
        #pragma unroll
        for (int r = 0; r < 8; r++) {
            a  += T[r].x * T[r].x + T[r].y * T[r].y;
            d0 += B[r].x * B[r].x + B[r].y * B[r].y;
        }
        a  += __shfl_xor_sync(FULL, a,  1);
        d0 += __shfl_xor_sync(FULL, d0, 1);
        nrmT = a; nrmB = d0;
    }

    // ---- one-sided Jacobi, round-robin, tracked norms ----
    const int NROUND = NSWEEP * 15;
    for (int it = 0; it < NROUND; it++) {
        const bool last = (it == NROUND - 1);

        // Gram off-diagonal conj(T).B over the 8 rows this lane holds
        float bx = 0.f, by = 0.f;
        #pragma unroll
        for (int r = 0; r < 8; r++) {
            bx += T[r].x * B[r].x + T[r].y * B[r].y;
            by += T[r].x * B[r].y - T[r].y * B[r].x;
        }
        bx += __shfl_xor_sync(FULL, bx, 1);
        by += __shfl_xor_sync(FULL, by, 1);

        // rotation params (one SIMD chain serves both matrices)
        float df  = nrmB - nrmT;
        float ab2 = bx * bx + by * by;
        float c = 1.f, wx = 0.f, wy = 0.f, delta = 0.f;
        if (ab2 > 1e-28f) {
            float rab = rsqrtf(ab2);
            float ab  = ab2 * rab;
            float tau = 0.5f * df * rab;
            float t2  = tau * tau + 1.f;
            float sq  = t2 * rsqrtf(t2);
            float den = fabsf(tau) + sq;
            float tt  = ((tau >= 0.f) ? 1.f : -1.f) * frcp(den);
            c  = rsqrtf(tt * tt + 1.f);
            float inv = tt * c * rab;
            wx = bx * inv; wy = by * inv;
            delta = tt * ab;
        }
        float a2 = nrmT - delta;
        float d2 = nrmB + delta;

        // column update + fused round-robin permutation (within lane halves)
        #pragma unroll
        for (int r = 0; r < 8; r++) {
            float tx = T[r].x, ty = T[r].y;
            float bxr = B[r].x, byr = B[r].y;
            float ntx = c * tx - (wx * bxr + wy * byr);
            float nty = c * ty - (wx * byr - wy * bxr);
            float nbx = (wx * tx - wy * ty) + c * bxr;
            float nby = (wx * ty + wy * tx) + c * byr;

            if (last) {
                T[r] = make_float2(ntx, nty);
                B[r] = make_float2(nbx, nby);
            } else {
                float selx = (g2 == 0) ? nbx : ntx;
                float sely = (g2 == 0) ? nby : nty;
                float upx = __shfl_sync(FULL, selx, lane - 2);
                float upy = __shfl_sync(FULL, sely, lane - 2);
                float dnx = __shfl_sync(FULL, nbx, lane + 2);
                float dny = __shfl_sync(FULL, nby, lane + 2);
                T[r] = (g2 == 0) ? make_float2(ntx, nty) : make_float2(upx, upy);
                B[r] = (g2 == 7) ? make_float2(ntx, nty) : make_float2(dnx, dny);
            }
        }
        if (last) {
            nrmT = a2; nrmB = d2;
        } else {
            float selN = (g2 == 0) ? d2 : a2;
            float upN  = __shfl_sync(FULL, selN, lane - 2);
            float dnN  = __shfl_sync(FULL, d2, lane + 2);
            nrmT = (g2 == 0) ? a2 : upN;
            nrmB = (g2 == 7) ? a2 : dnN;
        }
    }

    // ---- exact norms, min selection (within each 16-lane half) ----
    {
        float nT = 0.f, nB = 0.f;
        #pragma unroll
        for (int r = 0; r < 8; r++) {
            nT += T[r].x * T[r].x + T[r].y * T[r].y;
            nB += B[r].x * B[r].x + B[r].y * B[r].y;
        }
        nT += __shfl_xor_sync(FULL, nT, 1);
        nB += __shfl_xor_sync(FULL, nB, 1);

        float v; int tg;
        if (nB < nT) { v = nB; tg = 2 * g2 + 1; } else { v = nT; tg = 2 * g2; }
        #pragma unroll
        for (int o = 2; o <= 8; o <<= 1) {
            float ov = __shfl_xor_sync(FULL, v, o);
            int   ot = __shfl_xor_sync(FULL, tg, o);
            if (ov < v || (ov == v && ot < tg)) { v = ov; tg = ot; }
        }

        float sc = rsqrtf(v);
        if (g2 == (tg >> 1)) {
            #pragma unroll
            for (int r = 0; r < 8; r++) {
                float2 cv = (tg & 1) ? B[r] : T[r];
                spsi[w][m][2 * r + rl2] = make_float2(cv.x * sc, cv.y * sc);
            }
        }
    }
    __syncwarp();

    // ---- loss epilogue (full warp per matrix) ----
    float contrib = 0.f;
    #pragma unroll
    for (int mm = 0; mm < 2; mm++) {
        float2 psi = (lane < 16) ? spsi[w][mm][lane] : make_float2(0.f, 0.f);
        float2 tsum = psi;
        #pragma unroll
        for (int o = 16; o > 0; o >>= 1) {
            tsum.x += __shfl_xor_sync(FULL, tsum.x, o);
            tsum.y += __shfl_xor_sync(FULL, tsum.y, o);
        }

        float2 u  = make_float2(0.f, 0.f);
        float2 v2 = make_float2(0.f, 0.f);
        #pragma unroll
        for (int j2 = 0; j2 < 16; j2++) {
            float2 pj = spsi[w][mm][j2];
            float2 rr = g_r[lane * 16 + j2];
            u.x += rr.x * pj.x - rr.y * pj.y;
            u.y += rr.x * pj.y + rr.y * pj.x;
            float2 r2 = g_r2[lane * 16 + j2];
            v2.x += r2.x * pj.x - r2.y * pj.y;
            v2.y += r2.x * pj.y + r2.y * pj.x;
        }
        float pos = u.x  * tsum.x + u.y  * tsum.y;   // Re(u * conj(t))
        float e2  = v2.x * tsum.x + v2.y * tsum.y;
        float dlt = pos - x2[mm];
        contrib += dlt * dlt + LAM * (e2 - pos * pos);
    }

    #pragma unroll
    for (int o = 16; o > 0; o >>= 1)
        contrib += __shfl_xor_sync(FULL, contrib, o);

    if (lane == 0) {
        atomicAdd(&g_Z.acc, (double)contrib);
        __threadfence();
        unsigned int t = atomicAdd(&g_Z.cnt, 1u);
        if (t == (unsigned)(NTOT / 2 - 1)) {
            double total = atomicAdd(&g_Z.acc, 0.0);   // coherent final read
            out[0] = (float)(total * (1.0 / (double)NTOT));
        }
    }
}

extern "C" void kernel_launch(void* const* d_in, const int* in_sizes, int n_in,
                              void* d_out, int out_size) {
    const float* Ar = (const float*)d_in[0];
    const float* Ai = (const float*)d_in[1];
    const float* X  = (const float*)d_in[2];
    float* out = (float*)d_out;

    void* zptr = nullptr;
    cudaGetSymbolAddress(&zptr, g_Z);
    cudaMemsetAsync(zptr, 0, sizeof(ZeroBlock), 0);

    precompute_kernel<<<DD, 256>>>(Ar, Ai);
    solve_kernel<<<NTOT / (WPB * 2), WPB * 32>>>(X, out);
}